// round 2
// baseline (speedup 1.0000x reference)
#include <cuda_runtime.h>
#include <math.h>

#define BB 2
#define SS 1024
#define DDIM 512
#define HH 8
#define DH 64
#define FF 2048
#define MM (BB*SS)

// ---------------- scratch (no allocation allowed) ----------------
__device__ float g_xn[MM*DDIM];
__device__ float g_q [MM*DDIM];
__device__ float g_k [MM*DDIM];
__device__ float g_v [MM*DDIM];
__device__ float g_att[MM*DDIM];
__device__ float g_h [MM*DDIM];
__device__ float g_hn[MM*DDIM];
__device__ float g_f1[MM*FF];
__device__ float g_u [MM];
__device__ float g_lam[BB];
__device__ int   g_sp [BB];

// ---------------- lam / sparse flag ----------------
__global__ void lam_kernel(const float* __restrict__ u_prev){
    int b = threadIdx.x;
    if (b < BB){
        float lam = 10.0f * expf(-5.0f * u_prev[b]);
        g_lam[b] = lam;
        g_sp[b]  = (lam >= 1.0f) ? 1 : 0;
    }
}

// ---------------- LayerNorm: one block per row, 128 threads ----------------
__global__ void ln_kernel(const float* __restrict__ x, const float* __restrict__ g,
                          const float* __restrict__ be, float* __restrict__ y){
    int row = blockIdx.x;
    int t = threadIdx.x;                 // 0..127, 4 elems each
    const float* xr = x + (size_t)row * DDIM;
    float4 v = *(const float4*)(xr + t*4);
    float s  = v.x + v.y + v.z + v.w;
    float ss = v.x*v.x + v.y*v.y + v.z*v.z + v.w*v.w;
    #pragma unroll
    for (int o = 16; o; o >>= 1){
        s  += __shfl_xor_sync(0xffffffffu, s,  o);
        ss += __shfl_xor_sync(0xffffffffu, ss, o);
    }
    __shared__ float ps[4], pss[4];
    int w = t >> 5;
    if ((t & 31) == 0){ ps[w] = s; pss[w] = ss; }
    __syncthreads();
    s  = ps[0] + ps[1] + ps[2] + ps[3];
    ss = pss[0] + pss[1] + pss[2] + pss[3];
    float mean = s * (1.0f/DDIM);
    float var  = ss * (1.0f/DDIM) - mean*mean;
    float inv  = rsqrtf(var + 1e-5f);
    float4 gv = *(const float4*)(g  + t*4);
    float4 bv = *(const float4*)(be + t*4);
    float4 o;
    o.x = (v.x - mean)*inv*gv.x + bv.x;
    o.y = (v.y - mean)*inv*gv.y + bv.y;
    o.z = (v.z - mean)*inv*gv.z + bv.z;
    o.w = (v.w - mean)*inv*gv.w + bv.w;
    *(float4*)(y + (size_t)row * DDIM + t*4) = o;
}

// ---------------- tf32 helpers ----------------
__device__ __forceinline__ unsigned f2tf(float f){
    unsigned u;
    asm("cvt.rna.tf32.f32 %0, %1;" : "=r"(u) : "f"(f));
    return u;
}

__device__ __forceinline__ void mma8(float* c, const unsigned* a, const unsigned* b){
    asm volatile(
        "mma.sync.aligned.m16n8k8.row.col.f32.tf32.tf32.f32 "
        "{%0,%1,%2,%3}, {%4,%5,%6,%7}, {%8,%9}, {%0,%1,%2,%3};\n"
        : "+f"(c[0]), "+f"(c[1]), "+f"(c[2]), "+f"(c[3])
        : "r"(a[0]), "r"(a[1]), "r"(a[2]), "r"(a[3]), "r"(b[0]), "r"(b[1]));
}

__device__ __forceinline__ float gelu_exact(float v){
    return 0.5f * v * (1.0f + erff(v * 0.70710678118654752f));
}

// ---------------- tensor-core SGEMM (3xTF32): C[M,N] = A[M,K] @ W[N,K]^T ----------------
// BM=64, BN=64, BK=32, 128 threads (4 warps), warp tile 32x32.
// smem stored in fragment-permuted order:
//   A: [kstep(4)][mtile(4)][lane(32)][slot(4)]  -> one LDS.128 per A fragment
//   B: [kstep(4)][ntile(8)][lane(32)][slot(2)]  -> one LDS.64  per B fragment
template<bool GELU, bool RES>
__global__ void __launch_bounds__(128)
gemm_tc(const float* __restrict__ A, const float* __restrict__ W,
        const float* __restrict__ bias, const float* __restrict__ res,
        float* __restrict__ C, int Kn, int Nn){
    __shared__ unsigned Ah[4][4][32][4];
    __shared__ unsigned Al[4][4][32][4];
    __shared__ unsigned Bh[4][8][32][2];
    __shared__ unsigned Bl[4][8][32][2];

    const int tid = threadIdx.x;
    const int warp = tid >> 5, ln = tid & 31;
    const int wm = warp >> 1, wn = warp & 1;      // warp grid 2x2
    const int m0 = blockIdx.y * 64, n0 = blockIdx.x * 64;
    const int gid = ln >> 2, t4 = ln & 3;

    float acc[2][4][4];
    #pragma unroll
    for (int mt = 0; mt < 2; mt++)
        #pragma unroll
        for (int nt = 0; nt < 4; nt++)
            #pragma unroll
            for (int r = 0; r < 4; r++) acc[mt][nt][r] = 0.0f;

    for (int kt = 0; kt < Kn; kt += 32){
        // prefetch gmem tiles into registers (overlaps with prior compute)
        float4 av[4], wv[4];
        #pragma unroll
        for (int i = 0; i < 4; i++){
            int f = tid + i*128;             // 0..511
            int row = f >> 3;                // 0..63
            int kq  = (f & 7) << 2;          // 0,4,...,28
            av[i] = *(const float4*)(A + (size_t)(m0 + row)*Kn + kt + kq);
            wv[i] = *(const float4*)(W + (size_t)(n0 + row)*Kn + kt + kq);
        }
        __syncthreads();
        #pragma unroll
        for (int i = 0; i < 4; i++){
            int f = tid + i*128;
            int row = f >> 3;
            int kq  = (f & 7) << 2;
            int ks  = kq >> 3;               // kstep 0..3
            int sc  = (kq >> 2) & 1;         // col-half (c>=4)
            // A element (m=row, k in [kq,kq+4))
            int mt = row >> 4;
            int r  = row & 15;
            int slotA = (r >> 3) + (sc << 1);
            int lbA = (r & 7) << 2;
            float avv[4] = {av[i].x, av[i].y, av[i].z, av[i].w};
            #pragma unroll
            for (int j = 0; j < 4; j++){
                unsigned h = f2tf(avv[j]);
                float lo = avv[j] - __uint_as_float(h);
                Ah[ks][mt][lbA + j][slotA] = h;
                Al[ks][mt][lbA + j][slotA] = f2tf(lo);
            }
            // B element (n=row, k in [kq,kq+4))
            int nt = row >> 3;
            int lbB = (row & 7) << 2;
            float wvv[4] = {wv[i].x, wv[i].y, wv[i].z, wv[i].w};
            #pragma unroll
            for (int j = 0; j < 4; j++){
                unsigned h = f2tf(wvv[j]);
                float lo = wvv[j] - __uint_as_float(h);
                Bh[ks][nt][lbB + j][sc] = h;
                Bl[ks][nt][lbB + j][sc] = f2tf(lo);
            }
        }
        __syncthreads();

        #pragma unroll
        for (int ks = 0; ks < 4; ks++){
            unsigned ah[2][4], al[2][4], bh[4][2], bl[4][2];
            #pragma unroll
            for (int mt = 0; mt < 2; mt++){
                *(uint4*)ah[mt] = *(const uint4*)Ah[ks][wm*2 + mt][ln];
                *(uint4*)al[mt] = *(const uint4*)Al[ks][wm*2 + mt][ln];
            }
            #pragma unroll
            for (int nt = 0; nt < 4; nt++){
                *(uint2*)bh[nt] = *(const uint2*)Bh[ks][wn*4 + nt][ln];
                *(uint2*)bl[nt] = *(const uint2*)Bl[ks][wn*4 + nt][ln];
            }
            #pragma unroll
            for (int mt = 0; mt < 2; mt++)
                #pragma unroll
                for (int nt = 0; nt < 4; nt++){
                    mma8(acc[mt][nt], ah[mt], bh[nt]);   // hi*hi
                    mma8(acc[mt][nt], ah[mt], bl[nt]);   // hi*lo
                    mma8(acc[mt][nt], al[mt], bh[nt]);   // lo*hi
                }
        }
    }

    // epilogue
    #pragma unroll
    for (int mt = 0; mt < 2; mt++){
        #pragma unroll
        for (int rr = 0; rr < 2; rr++){
            int m = m0 + wm*32 + mt*16 + gid + rr*8;
            #pragma unroll
            for (int nt = 0; nt < 4; nt++){
                int n = n0 + wn*32 + nt*8 + t4*2;
                float2 o;
                o.x = acc[mt][nt][rr*2 + 0];
                o.y = acc[mt][nt][rr*2 + 1];
                float2 bv = *(const float2*)(bias + n);
                o.x += bv.x; o.y += bv.y;
                if (RES){
                    float2 rv = *(const float2*)(res + (size_t)m*Nn + n);
                    o.x += rv.x; o.y += rv.y;
                }
                if (GELU){
                    o.x = gelu_exact(o.x);
                    o.y = gelu_exact(o.y);
                }
                *(float2*)(C + (size_t)m*Nn + n) = o;
            }
        }
    }
}

// ---------------- unified flash attention (dense bias OR sparse band) ----------------
#define APAD 68
__global__ void attn_kernel(const float* __restrict__ Q, const float* __restrict__ K,
                            const float* __restrict__ V, float* __restrict__ O){
    extern __shared__ float sm[];
    float* Qt = sm;
    float* Kt = sm + 64*APAD;
    float* Vs = sm + 2*64*APAD;

    const int bh = blockIdx.y;
    const int b = bh / HH, h = bh % HH;
    const int q0 = blockIdx.x * 64;
    const float lam = g_lam[b];
    const int sp = g_sp[b];
    const int tid = threadIdx.x;
    const int ty = tid >> 4, tx = tid & 15;

    #pragma unroll
    for (int it = 0; it < 4; it++){
        int flat = tid + it*256;
        int r = flat >> 4, c4 = (flat & 15) << 2;
        float4 v = *(const float4*)(Q + (size_t)(b*SS + q0 + r)*DDIM + h*DH + c4);
        Qt[(c4+0)*APAD + r] = v.x;
        Qt[(c4+1)*APAD + r] = v.y;
        Qt[(c4+2)*APAD + r] = v.z;
        Qt[(c4+3)*APAD + r] = v.w;
    }

    float acc[4][4];
    float mrow[4], lrow[4];
    #pragma unroll
    for (int i = 0; i < 4; i++){
        mrow[i] = -INFINITY; lrow[i] = 0.0f;
        #pragma unroll
        for (int j = 0; j < 4; j++) acc[i][j] = 0.0f;
    }

    int klo = 0, khi = SS/64;
    if (sp){
        int lo = q0 - 51; if (lo < 0) lo = 0;
        int hi = q0 + 114; if (hi > SS-1) hi = SS-1;
        klo = lo >> 6; khi = (hi >> 6) + 1;
    }

    for (int kb = klo; kb < khi; kb++){
        __syncthreads();
        #pragma unroll
        for (int it = 0; it < 4; it++){
            int flat = tid + it*256;
            int r = flat >> 4, c4 = (flat & 15) << 2;
            float4 kv = *(const float4*)(K + (size_t)(b*SS + kb*64 + r)*DDIM + h*DH + c4);
            Kt[(c4+0)*APAD + r] = kv.x;
            Kt[(c4+1)*APAD + r] = kv.y;
            Kt[(c4+2)*APAD + r] = kv.z;
            Kt[(c4+3)*APAD + r] = kv.w;
            float4 vv = *(const float4*)(V + (size_t)(b*SS + kb*64 + r)*DDIM + h*DH + c4);
            *(float4*)(Vs + r*APAD + c4) = vv;
        }
        __syncthreads();

        float s[4][4];
        #pragma unroll
        for (int i = 0; i < 4; i++)
            #pragma unroll
            for (int j = 0; j < 4; j++) s[i][j] = 0.0f;
        #pragma unroll 8
        for (int kk = 0; kk < 64; kk++){
            float4 qa = *(const float4*)(Qt + kk*APAD + ty*4);
            float4 kv = *(const float4*)(Kt + kk*APAD + tx*4);
            float qv[4] = {qa.x,qa.y,qa.z,qa.w};
            float kw[4] = {kv.x,kv.y,kv.z,kv.w};
            #pragma unroll
            for (int i = 0; i < 4; i++)
                #pragma unroll
                for (int j = 0; j < 4; j++)
                    s[i][j] += qv[i] * kw[j];
        }

        float p[4][4];
        #pragma unroll
        for (int i = 0; i < 4; i++){
            int qg = q0 + ty*4 + i;
            float val[4]; bool vld[4];
            float rm = -INFINITY;
            #pragma unroll
            for (int j = 0; j < 4; j++){
                int kg = kb*64 + tx*4 + j;
                bool inb = (kg >= qg - 51) && (kg <= qg + 51);
                float vv = s[i][j] * 0.125f;
                if (sp){ vld[j] = inb; }
                else   { vld[j] = true; if (!inb) vv -= lam; }
                val[j] = vv;
                if (vld[j]) rm = fmaxf(rm, vv);
            }
            #pragma unroll
            for (int o = 8; o; o >>= 1)
                rm = fmaxf(rm, __shfl_xor_sync(0xffffffffu, rm, o));
            float mnew = fmaxf(mrow[i], rm);
            float sf = (mrow[i] == mnew) ? 1.0f : expf(mrow[i] - mnew);
            float rs = 0.0f;
            #pragma unroll
            for (int j = 0; j < 4; j++){
                p[i][j] = vld[j] ? expf(val[j] - mnew) : 0.0f;
                rs += p[i][j];
            }
            #pragma unroll
            for (int o = 8; o; o >>= 1)
                rs += __shfl_xor_sync(0xffffffffu, rs, o);
            lrow[i] = lrow[i] * sf + rs;
            mrow[i] = mnew;
            #pragma unroll
            for (int j = 0; j < 4; j++) acc[i][j] *= sf;
        }
        __syncthreads();
        #pragma unroll
        for (int i = 0; i < 4; i++)
            #pragma unroll
            for (int j = 0; j < 4; j++)
                Kt[(tx*4+j)*APAD + (ty*4+i)] = p[i][j];
        __syncthreads();

        #pragma unroll 8
        for (int kk = 0; kk < 64; kk++){
            float4 pv = *(const float4*)(Kt + kk*APAD + ty*4);
            float4 vv = *(const float4*)(Vs + kk*APAD + tx*4);
            float pa[4] = {pv.x,pv.y,pv.z,pv.w};
            float vb[4] = {vv.x,vv.y,vv.z,vv.w};
            #pragma unroll
            for (int i = 0; i < 4; i++)
                #pragma unroll
                for (int j = 0; j < 4; j++)
                    acc[i][j] += pa[i] * vb[j];
        }
    }

    #pragma unroll
    for (int i = 0; i < 4; i++){
        float inv = 1.0f / lrow[i];
        float4 o;
        o.x = acc[i][0]*inv; o.y = acc[i][1]*inv;
        o.z = acc[i][2]*inv; o.w = acc[i][3]*inv;
        *(float4*)(O + (size_t)(b*SS + q0 + ty*4 + i)*DDIM + h*DH + tx*4) = o;
    }
}

// ---------------- per-row u, then per-batch mean ----------------
__global__ void u_row_kernel(const float* __restrict__ outp, const float* __restrict__ x){
    int row = blockIdx.x;
    int t = threadIdx.x;
    float4 ov = *(const float4*)(outp + (size_t)row*DDIM + t*4);
    float4 xv = *(const float4*)(x    + (size_t)row*DDIM + t*4);
    float dx = ov.x - xv.x, dy = ov.y - xv.y, dz = ov.z - xv.z, dw = ov.w - xv.w;
    float d2 = dx*dx + dy*dy + dz*dz + dw*dw;
    float x2 = xv.x*xv.x + xv.y*xv.y + xv.z*xv.z + xv.w*xv.w;
    #pragma unroll
    for (int o = 16; o; o >>= 1){
        d2 += __shfl_xor_sync(0xffffffffu, d2, o);
        x2 += __shfl_xor_sync(0xffffffffu, x2, o);
    }
    __shared__ float pd[4], px[4];
    int w = t >> 5;
    if ((t & 31) == 0){ pd[w] = d2; px[w] = x2; }
    __syncthreads();
    if (t == 0){
        d2 = pd[0]+pd[1]+pd[2]+pd[3];
        x2 = px[0]+px[1]+px[2]+px[3];
        g_u[row] = sqrtf(d2) / (sqrtf(x2) + 1e-8f);
    }
}

__global__ void u_mean_kernel(float* __restrict__ outp, int out_size){
    int b = blockIdx.x;
    int t = threadIdx.x;
    float s = 0.0f;
    for (int i = t; i < SS; i += 256) s += g_u[b*SS + i];
    #pragma unroll
    for (int o = 16; o; o >>= 1) s += __shfl_xor_sync(0xffffffffu, s, o);
    __shared__ float ps[8];
    int w = t >> 5;
    if ((t & 31) == 0) ps[w] = s;
    __syncthreads();
    if (t == 0){
        s = 0.0f;
        #pragma unroll
        for (int i = 0; i < 8; i++) s += ps[i];
        int idx = MM*DDIM + b;
        if (idx < out_size) outp[idx] = s * (1.0f/SS);
    }
}

// ---------------- launch ----------------
extern "C" void kernel_launch(void* const* d_in, const int* in_sizes, int n_in,
                              void* d_out, int out_size){
    const float* x      = (const float*)d_in[0];
    const float* u_prev = (const float*)d_in[1];
    const float* wq = (const float*)d_in[2];  const float* bq = (const float*)d_in[3];
    const float* wk = (const float*)d_in[4];  const float* bk = (const float*)d_in[5];
    const float* wv = (const float*)d_in[6];  const float* bv = (const float*)d_in[7];
    const float* wo = (const float*)d_in[8];  const float* bo = (const float*)d_in[9];
    const float* ln1g = (const float*)d_in[10]; const float* ln1b = (const float*)d_in[11];
    const float* ln2g = (const float*)d_in[12]; const float* ln2b = (const float*)d_in[13];
    const float* w1 = (const float*)d_in[14]; const float* b1 = (const float*)d_in[15];
    const float* w2 = (const float*)d_in[16]; const float* b2 = (const float*)d_in[17];
    float* outp = (float*)d_out;

    float *p_xn, *p_q, *p_k, *p_v, *p_att, *p_h, *p_hn, *p_f1;
    cudaGetSymbolAddress((void**)&p_xn,  g_xn);
    cudaGetSymbolAddress((void**)&p_q,   g_q);
    cudaGetSymbolAddress((void**)&p_k,   g_k);
    cudaGetSymbolAddress((void**)&p_v,   g_v);
    cudaGetSymbolAddress((void**)&p_att, g_att);
    cudaGetSymbolAddress((void**)&p_h,   g_h);
    cudaGetSymbolAddress((void**)&p_hn,  g_hn);
    cudaGetSymbolAddress((void**)&p_f1,  g_f1);

    const int attn_smem = 3 * 64 * APAD * 4;
    cudaFuncSetAttribute(attn_kernel, cudaFuncAttributeMaxDynamicSharedMemorySize, attn_smem);

    lam_kernel<<<1, 32>>>(u_prev);
    ln_kernel<<<MM, 128>>>(x, ln1g, ln1b, p_xn);

    dim3 gp(DDIM/64, MM/64);                   // (8,32) = 256 blocks
    gemm_tc<false,false><<<gp, 128>>>(p_xn, wq, bq, nullptr, p_q, DDIM, DDIM);
    gemm_tc<false,false><<<gp, 128>>>(p_xn, wk, bk, nullptr, p_k, DDIM, DDIM);
    gemm_tc<false,false><<<gp, 128>>>(p_xn, wv, bv, nullptr, p_v, DDIM, DDIM);

    attn_kernel<<<dim3(SS/64, BB*HH), 256, attn_smem>>>(p_q, p_k, p_v, p_att);

    gemm_tc<false,true><<<gp, 128>>>(p_att, wo, bo, x, p_h, DDIM, DDIM);

    ln_kernel<<<MM, 128>>>(p_h, ln2g, ln2b, p_hn);

    gemm_tc<true,false><<<dim3(FF/64, MM/64), 128>>>(p_hn, w1, b1, nullptr, p_f1, DDIM, FF);
    gemm_tc<false,true><<<gp, 128>>>(p_f1, w2, b2, p_h, outp, FF, DDIM);

    u_row_kernel<<<MM, 128>>>(outp, x);
    u_mean_kernel<<<BB, 256>>>(outp, out_size);
}

// round 3
// speedup vs baseline: 1.9507x; 1.9507x over previous
#include <cuda_runtime.h>
#include <cuda_bf16.h>
#include <math.h>

#define BB 2
#define SS 1024
#define DDIM 512
#define HH 8
#define DH 64
#define FF 2048
#define MM (BB*SS)

// ---------------- scratch (no allocation allowed) ----------------
__device__ float g_xn[MM*DDIM];
__device__ float g_q [MM*DDIM];
__device__ float g_k [MM*DDIM];
__device__ float g_v [MM*DDIM];
__device__ float g_att[MM*DDIM];
__device__ float g_h [MM*DDIM];
__device__ float g_hn[MM*DDIM];
__device__ float g_f1[MM*FF];
__device__ float g_u [MM];
__device__ float g_lam[BB];
__device__ int   g_sp [BB];

// ---------------- lam / sparse flag ----------------
__global__ void lam_kernel(const float* __restrict__ u_prev){
    int b = threadIdx.x;
    if (b < BB){
        float lam = 10.0f * expf(-5.0f * u_prev[b]);
        g_lam[b] = lam;
        g_sp[b]  = (lam >= 1.0f) ? 1 : 0;
    }
}

// ---------------- LayerNorm ----------------
__global__ void ln_kernel(const float* __restrict__ x, const float* __restrict__ g,
                          const float* __restrict__ be, float* __restrict__ y){
    int row = blockIdx.x;
    int t = threadIdx.x;
    const float* xr = x + (size_t)row * DDIM;
    float4 v = *(const float4*)(xr + t*4);
    float s  = v.x + v.y + v.z + v.w;
    float ss = v.x*v.x + v.y*v.y + v.z*v.z + v.w*v.w;
    #pragma unroll
    for (int o = 16; o; o >>= 1){
        s  += __shfl_xor_sync(0xffffffffu, s,  o);
        ss += __shfl_xor_sync(0xffffffffu, ss, o);
    }
    __shared__ float ps[4], pss[4];
    int w = t >> 5;
    if ((t & 31) == 0){ ps[w] = s; pss[w] = ss; }
    __syncthreads();
    s  = ps[0] + ps[1] + ps[2] + ps[3];
    ss = pss[0] + pss[1] + pss[2] + pss[3];
    float mean = s * (1.0f/DDIM);
    float var  = ss * (1.0f/DDIM) - mean*mean;
    float inv  = rsqrtf(var + 1e-5f);
    float4 gv = *(const float4*)(g  + t*4);
    float4 bv = *(const float4*)(be + t*4);
    float4 o;
    o.x = (v.x - mean)*inv*gv.x + bv.x;
    o.y = (v.y - mean)*inv*gv.y + bv.y;
    o.z = (v.z - mean)*inv*gv.z + bv.z;
    o.w = (v.w - mean)*inv*gv.w + bv.w;
    *(float4*)(y + (size_t)row * DDIM + t*4) = o;
}

// ---------------- bf16 split helpers ----------------
__device__ __forceinline__ void bsplit(float x0, float x1, unsigned &hw, unsigned &lw){
    asm("cvt.rn.bf16x2.f32 %0, %1, %2;" : "=r"(hw) : "f"(x1), "f"(x0));
    float h0 = __uint_as_float(hw << 16);
    float h1 = __uint_as_float(hw & 0xffff0000u);
    float l0 = x0 - h0, l1 = x1 - h1;
    asm("cvt.rn.bf16x2.f32 %0, %1, %2;" : "=r"(lw) : "f"(l1), "f"(l0));
}

__device__ __forceinline__ void mma16(float* c, const unsigned* a, const unsigned* b){
    asm volatile(
        "mma.sync.aligned.m16n8k16.row.col.f32.bf16.bf16.f32 "
        "{%0,%1,%2,%3}, {%4,%5,%6,%7}, {%8,%9}, {%0,%1,%2,%3};\n"
        : "+f"(c[0]), "+f"(c[1]), "+f"(c[2]), "+f"(c[3])
        : "r"(a[0]), "r"(a[1]), "r"(a[2]), "r"(a[3]), "r"(b[0]), "r"(b[1]));
}

__device__ __forceinline__ float gelu_exact(float v){
    return 0.5f * v * (1.0f + erff(v * 0.70710678118654752f));
}

// ---------------- bf16x4 tensor-core GEMM body ----------------
// C[M,N] = A[M,K] @ W[N,K]^T (+bias)(+res)(gelu), fp32 in/out.
// BMx64 tile, BK=32, 128 threads (4 warps, 2x2), warp tile (BM/2)x32.
// smem fragment-permuted: one LDS.128 per A frag, LDS.64 per B frag.
template<int BM, bool GELU, bool RES>
__device__ __forceinline__ void gemm_body(
        const float* __restrict__ A, const float* __restrict__ W,
        const float* __restrict__ bias, const float* __restrict__ res,
        float* __restrict__ C, int Kn, int Nn, int m0, int n0){
    constexpr int MTILES = BM/16;      // 16-row tiles per block
    constexpr int WMT    = MTILES/2;   // per-warp mtiles
    constexpr int AIT    = BM/16;      // A staging iters (BM*8 float4 / 128 thr)

    __shared__ unsigned Ah[2][MTILES][32][4];
    __shared__ unsigned Al[2][MTILES][32][4];
    __shared__ unsigned Bh[2][8][32][2];
    __shared__ unsigned Bl[2][8][32][2];

    const int tid = threadIdx.x;
    const int warp = tid >> 5, ln = tid & 31;
    const int wm = warp >> 1, wn = warp & 1;
    const int gid = ln >> 2, t4 = ln & 3;

    float acc[WMT][4][4];
    #pragma unroll
    for (int mt = 0; mt < WMT; mt++)
        #pragma unroll
        for (int nt = 0; nt < 4; nt++)
            #pragma unroll
            for (int r = 0; r < 4; r++) acc[mt][nt][r] = 0.0f;

    for (int kt = 0; kt < Kn; kt += 32){
        float4 av[AIT], wv4[4];
        #pragma unroll
        for (int i = 0; i < AIT; i++){
            int f = tid + i*128;
            int row = f >> 3, kq = (f & 7) << 2;
            av[i] = *(const float4*)(A + (size_t)(m0 + row)*Kn + kt + kq);
        }
        #pragma unroll
        for (int i = 0; i < 4; i++){
            int f = tid + i*128;
            int row = f >> 3, kq = (f & 7) << 2;
            wv4[i] = *(const float4*)(W + (size_t)(n0 + row)*Kn + kt + kq);
        }
        __syncthreads();
        #pragma unroll
        for (int i = 0; i < AIT; i++){
            int f = tid + i*128;
            int row = f >> 3, kq = (f & 7) << 2;
            int ks = kq >> 4, kk = kq & 15;
            int mt = row >> 4, rr = row & 15;
            int slot = ((rr >> 3) & 1) + (((kk >> 3) & 1) << 1);
            int lane = (rr & 7)*4 + ((kk & 7) >> 1);
            unsigned h0, l0, h1, l1;
            bsplit(av[i].x, av[i].y, h0, l0);
            bsplit(av[i].z, av[i].w, h1, l1);
            Ah[ks][mt][lane  ][slot] = h0;
            Ah[ks][mt][lane+1][slot] = h1;
            Al[ks][mt][lane  ][slot] = l0;
            Al[ks][mt][lane+1][slot] = l1;
        }
        #pragma unroll
        for (int i = 0; i < 4; i++){
            int f = tid + i*128;
            int row = f >> 3, kq = (f & 7) << 2;
            int ks = kq >> 4, kk = kq & 15;
            int nt = row >> 3;
            int slot = (kk >> 3) & 1;
            int lane = (row & 7)*4 + ((kk & 7) >> 1);
            unsigned h0, l0, h1, l1;
            bsplit(wv4[i].x, wv4[i].y, h0, l0);
            bsplit(wv4[i].z, wv4[i].w, h1, l1);
            Bh[ks][nt][lane  ][slot] = h0;
            Bh[ks][nt][lane+1][slot] = h1;
            Bl[ks][nt][lane  ][slot] = l0;
            Bl[ks][nt][lane+1][slot] = l1;
        }
        __syncthreads();

        #pragma unroll
        for (int ks = 0; ks < 2; ks++){
            unsigned ah[WMT][4], al[WMT][4], bh[4][2], bl[4][2];
            #pragma unroll
            for (int mt = 0; mt < WMT; mt++){
                *(uint4*)ah[mt] = *(const uint4*)Ah[ks][wm*WMT + mt][ln];
                *(uint4*)al[mt] = *(const uint4*)Al[ks][wm*WMT + mt][ln];
            }
            #pragma unroll
            for (int nt = 0; nt < 4; nt++){
                *(uint2*)bh[nt] = *(const uint2*)Bh[ks][wn*4 + nt][ln];
                *(uint2*)bl[nt] = *(const uint2*)Bl[ks][wn*4 + nt][ln];
            }
            #pragma unroll
            for (int mt = 0; mt < WMT; mt++)
                #pragma unroll
                for (int nt = 0; nt < 4; nt++){
                    mma16(acc[mt][nt], ah[mt], bh[nt]);
                    mma16(acc[mt][nt], ah[mt], bl[nt]);
                    mma16(acc[mt][nt], al[mt], bh[nt]);
                    mma16(acc[mt][nt], al[mt], bl[nt]);
                }
        }
    }

    #pragma unroll
    for (int mt = 0; mt < WMT; mt++){
        #pragma unroll
        for (int rr = 0; rr < 2; rr++){
            int m = m0 + wm*(BM/2) + mt*16 + gid + rr*8;
            #pragma unroll
            for (int nt = 0; nt < 4; nt++){
                int n = n0 + wn*32 + nt*8 + t4*2;
                float2 o;
                o.x = acc[mt][nt][rr*2 + 0];
                o.y = acc[mt][nt][rr*2 + 1];
                float2 bv = *(const float2*)(bias + n);
                o.x += bv.x; o.y += bv.y;
                if (RES){
                    float2 rv = *(const float2*)(res + (size_t)m*Nn + n);
                    o.x += rv.x; o.y += rv.y;
                }
                if (GELU){
                    o.x = gelu_exact(o.x);
                    o.y = gelu_exact(o.y);
                }
                *(float2*)(C + (size_t)m*Nn + n) = o;
            }
        }
    }
}

// ---------------- GEMM kernels ----------------
__global__ void __launch_bounds__(128)
qkv_kernel(const float* __restrict__ xn,
           const float* __restrict__ wq, const float* __restrict__ wk, const float* __restrict__ wv,
           const float* __restrict__ bq, const float* __restrict__ bk, const float* __restrict__ bv,
           float* __restrict__ q, float* __restrict__ k, float* __restrict__ v){
    int sel = blockIdx.x >> 3;
    int n0 = (blockIdx.x & 7) << 6;
    const float* W    = (sel == 0) ? wq : (sel == 1) ? wk : wv;
    const float* bias = (sel == 0) ? bq : (sel == 1) ? bk : bv;
    float* C          = (sel == 0) ? q  : (sel == 1) ? k  : v;
    gemm_body<64,false,false>(xn, W, bias, nullptr, C, DDIM, DDIM, blockIdx.y*64, n0);
}

template<bool GELU, bool RES>
__global__ void __launch_bounds__(128)
gemm64(const float* __restrict__ A, const float* __restrict__ W,
       const float* __restrict__ bias, const float* __restrict__ res,
       float* __restrict__ C, int Kn, int Nn){
    gemm_body<64,GELU,RES>(A, W, bias, res, C, Kn, Nn, blockIdx.y*64, blockIdx.x*64);
}

template<bool GELU, bool RES>
__global__ void __launch_bounds__(128)
gemm32(const float* __restrict__ A, const float* __restrict__ W,
       const float* __restrict__ bias, const float* __restrict__ res,
       float* __restrict__ C, int Kn, int Nn){
    gemm_body<32,GELU,RES>(A, W, bias, res, C, Kn, Nn, blockIdx.y*32, blockIdx.x*64);
}

// ---------------- unified flash attention (dense bias OR sparse band) ----------------
#define APAD 68
__global__ void attn_kernel(const float* __restrict__ Q, const float* __restrict__ K,
                            const float* __restrict__ V, float* __restrict__ O){
    extern __shared__ float sm[];
    float* Qt = sm;
    float* Kt = sm + 64*APAD;
    float* Vs = sm + 2*64*APAD;

    const int bh = blockIdx.y;
    const int b = bh / HH, h = bh % HH;
    const int q0 = blockIdx.x * 64;
    const float lam = g_lam[b];
    const int sp = g_sp[b];
    const int tid = threadIdx.x;
    const int ty = tid >> 4, tx = tid & 15;

    #pragma unroll
    for (int it = 0; it < 4; it++){
        int flat = tid + it*256;
        int r = flat >> 4, c4 = (flat & 15) << 2;
        float4 v = *(const float4*)(Q + (size_t)(b*SS + q0 + r)*DDIM + h*DH + c4);
        Qt[(c4+0)*APAD + r] = v.x;
        Qt[(c4+1)*APAD + r] = v.y;
        Qt[(c4+2)*APAD + r] = v.z;
        Qt[(c4+3)*APAD + r] = v.w;
    }

    float acc[4][4];
    float mrow[4], lrow[4];
    #pragma unroll
    for (int i = 0; i < 4; i++){
        mrow[i] = -INFINITY; lrow[i] = 0.0f;
        #pragma unroll
        for (int j = 0; j < 4; j++) acc[i][j] = 0.0f;
    }

    int klo = 0, khi = SS/64;
    if (sp){
        int lo = q0 - 51; if (lo < 0) lo = 0;
        int hi = q0 + 114; if (hi > SS-1) hi = SS-1;
        klo = lo >> 6; khi = (hi >> 6) + 1;
    }

    for (int kb = klo; kb < khi; kb++){
        __syncthreads();
        #pragma unroll
        for (int it = 0; it < 4; it++){
            int flat = tid + it*256;
            int r = flat >> 4, c4 = (flat & 15) << 2;
            float4 kv = *(const float4*)(K + (size_t)(b*SS + kb*64 + r)*DDIM + h*DH + c4);
            Kt[(c4+0)*APAD + r] = kv.x;
            Kt[(c4+1)*APAD + r] = kv.y;
            Kt[(c4+2)*APAD + r] = kv.z;
            Kt[(c4+3)*APAD + r] = kv.w;
            float4 vv = *(const float4*)(V + (size_t)(b*SS + kb*64 + r)*DDIM + h*DH + c4);
            *(float4*)(Vs + r*APAD + c4) = vv;
        }
        __syncthreads();

        float s[4][4];
        #pragma unroll
        for (int i = 0; i < 4; i++)
            #pragma unroll
            for (int j = 0; j < 4; j++) s[i][j] = 0.0f;
        #pragma unroll 8
        for (int kk = 0; kk < 64; kk++){
            float4 qa = *(const float4*)(Qt + kk*APAD + ty*4);
            float4 kv = *(const float4*)(Kt + kk*APAD + tx*4);
            float qv[4] = {qa.x,qa.y,qa.z,qa.w};
            float kw[4] = {kv.x,kv.y,kv.z,kv.w};
            #pragma unroll
            for (int i = 0; i < 4; i++)
                #pragma unroll
                for (int j = 0; j < 4; j++)
                    s[i][j] += qv[i] * kw[j];
        }

        float p[4][4];
        #pragma unroll
        for (int i = 0; i < 4; i++){
            int qg = q0 + ty*4 + i;
            float val[4]; bool vld[4];
            float rm = -INFINITY;
            #pragma unroll
            for (int j = 0; j < 4; j++){
                int kg = kb*64 + tx*4 + j;
                bool inb = (kg >= qg - 51) && (kg <= qg + 51);
                float vv = s[i][j] * 0.125f;
                if (sp){ vld[j] = inb; }
                else   { vld[j] = true; if (!inb) vv -= lam; }
                val[j] = vv;
                if (vld[j]) rm = fmaxf(rm, vv);
            }
            #pragma unroll
            for (int o = 8; o; o >>= 1)
                rm = fmaxf(rm, __shfl_xor_sync(0xffffffffu, rm, o));
            float mnew = fmaxf(mrow[i], rm);
            float sf = (mrow[i] == mnew) ? 1.0f : expf(mrow[i] - mnew);
            float rs = 0.0f;
            #pragma unroll
            for (int j = 0; j < 4; j++){
                p[i][j] = vld[j] ? expf(val[j] - mnew) : 0.0f;
                rs += p[i][j];
            }
            #pragma unroll
            for (int o = 8; o; o >>= 1)
                rs += __shfl_xor_sync(0xffffffffu, rs, o);
            lrow[i] = lrow[i] * sf + rs;
            mrow[i] = mnew;
            #pragma unroll
            for (int j = 0; j < 4; j++) acc[i][j] *= sf;
        }
        __syncthreads();
        #pragma unroll
        for (int i = 0; i < 4; i++)
            #pragma unroll
            for (int j = 0; j < 4; j++)
                Kt[(tx*4+j)*APAD + (ty*4+i)] = p[i][j];
        __syncthreads();

        #pragma unroll 8
        for (int kk = 0; kk < 64; kk++){
            float4 pv = *(const float4*)(Kt + kk*APAD + ty*4);
            float4 vv = *(const float4*)(Vs + kk*APAD + tx*4);
            float pa[4] = {pv.x,pv.y,pv.z,pv.w};
            float vb[4] = {vv.x,vv.y,vv.z,vv.w};
            #pragma unroll
            for (int i = 0; i < 4; i++)
                #pragma unroll
                for (int j = 0; j < 4; j++)
                    acc[i][j] += pa[i] * vb[j];
        }
    }

    #pragma unroll
    for (int i = 0; i < 4; i++){
        float inv = 1.0f / lrow[i];
        float4 o;
        o.x = acc[i][0]*inv; o.y = acc[i][1]*inv;
        o.z = acc[i][2]*inv; o.w = acc[i][3]*inv;
        *(float4*)(O + (size_t)(b*SS + q0 + ty*4 + i)*DDIM + h*DH + tx*4) = o;
    }
}

// ---------------- per-row u, then per-batch mean ----------------
__global__ void u_row_kernel(const float* __restrict__ outp, const float* __restrict__ x){
    int row = blockIdx.x;
    int t = threadIdx.x;
    float4 ov = *(const float4*)(outp + (size_t)row*DDIM + t*4);
    float4 xv = *(const float4*)(x    + (size_t)row*DDIM + t*4);
    float dx = ov.x - xv.x, dy = ov.y - xv.y, dz = ov.z - xv.z, dw = ov.w - xv.w;
    float d2 = dx*dx + dy*dy + dz*dz + dw*dw;
    float x2 = xv.x*xv.x + xv.y*xv.y + xv.z*xv.z + xv.w*xv.w;
    #pragma unroll
    for (int o = 16; o; o >>= 1){
        d2 += __shfl_xor_sync(0xffffffffu, d2, o);
        x2 += __shfl_xor_sync(0xffffffffu, x2, o);
    }
    __shared__ float pd[4], px[4];
    int w = t >> 5;
    if ((t & 31) == 0){ pd[w] = d2; px[w] = x2; }
    __syncthreads();
    if (t == 0){
        d2 = pd[0]+pd[1]+pd[2]+pd[3];
        x2 = px[0]+px[1]+px[2]+px[3];
        g_u[row] = sqrtf(d2) / (sqrtf(x2) + 1e-8f);
    }
}

__global__ void u_mean_kernel(float* __restrict__ outp, int out_size){
    int b = blockIdx.x;
    int t = threadIdx.x;
    float s = 0.0f;
    for (int i = t; i < SS; i += 256) s += g_u[b*SS + i];
    #pragma unroll
    for (int o = 16; o; o >>= 1) s += __shfl_xor_sync(0xffffffffu, s, o);
    __shared__ float ps[8];
    int w = t >> 5;
    if ((t & 31) == 0) ps[w] = s;
    __syncthreads();
    if (t == 0){
        s = 0.0f;
        #pragma unroll
        for (int i = 0; i < 8; i++) s += ps[i];
        int idx = MM*DDIM + b;
        if (idx < out_size) outp[idx] = s * (1.0f/SS);
    }
}

// ---------------- launch ----------------
extern "C" void kernel_launch(void* const* d_in, const int* in_sizes, int n_in,
                              void* d_out, int out_size){
    const float* x      = (const float*)d_in[0];
    const float* u_prev = (const float*)d_in[1];
    const float* wq = (const float*)d_in[2];  const float* bq = (const float*)d_in[3];
    const float* wk = (const float*)d_in[4];  const float* bk = (const float*)d_in[5];
    const float* wv = (const float*)d_in[6];  const float* bv = (const float*)d_in[7];
    const float* wo = (const float*)d_in[8];  const float* bo = (const float*)d_in[9];
    const float* ln1g = (const float*)d_in[10]; const float* ln1b = (const float*)d_in[11];
    const float* ln2g = (const float*)d_in[12]; const float* ln2b = (const float*)d_in[13];
    const float* w1 = (const float*)d_in[14]; const float* b1 = (const float*)d_in[15];
    const float* w2 = (const float*)d_in[16]; const float* b2 = (const float*)d_in[17];
    float* outp = (float*)d_out;

    float *p_xn, *p_q, *p_k, *p_v, *p_att, *p_h, *p_hn, *p_f1;
    cudaGetSymbolAddress((void**)&p_xn,  g_xn);
    cudaGetSymbolAddress((void**)&p_q,   g_q);
    cudaGetSymbolAddress((void**)&p_k,   g_k);
    cudaGetSymbolAddress((void**)&p_v,   g_v);
    cudaGetSymbolAddress((void**)&p_att, g_att);
    cudaGetSymbolAddress((void**)&p_h,   g_h);
    cudaGetSymbolAddress((void**)&p_hn,  g_hn);
    cudaGetSymbolAddress((void**)&p_f1,  g_f1);

    const int attn_smem = 3 * 64 * APAD * 4;
    cudaFuncSetAttribute(attn_kernel, cudaFuncAttributeMaxDynamicSharedMemorySize, attn_smem);

    lam_kernel<<<1, 32>>>(u_prev);
    ln_kernel<<<MM, 128>>>(x, ln1g, ln1b, p_xn);

    // fused QKV: 24 x 32 = 768 blocks
    qkv_kernel<<<dim3(24, MM/64), 128>>>(p_xn, wq, wk, wv, bq, bk, bv, p_q, p_k, p_v);

    attn_kernel<<<dim3(SS/64, BB*HH), 256, attn_smem>>>(p_q, p_k, p_v, p_att);

    // Wo: N=512 -> BM=32 for 512 blocks
    gemm32<false,true><<<dim3(DDIM/64, MM/32), 128>>>(p_att, wo, bo, x, p_h, DDIM, DDIM);

    ln_kernel<<<MM, 128>>>(p_h, ln2g, ln2b, p_hn);

    // FFN1: 32 x 32 = 1024 blocks
    gemm64<true,false><<<dim3(FF/64, MM/64), 128>>>(p_hn, w1, b1, nullptr, p_f1, DDIM, FF);
    // FFN2: N=512 -> BM=32 for 512 blocks
    gemm32<false,true><<<dim3(DDIM/64, MM/32), 128>>>(p_f1, w2, b2, p_h, outp, FF, DDIM);

    u_row_kernel<<<MM, 128>>>(outp, x);
    u_mean_kernel<<<BB, 256>>>(outp, out_size);
}

// round 4
// speedup vs baseline: 2.2339x; 1.1452x over previous
#include <cuda_runtime.h>
#include <cuda_bf16.h>
#include <math.h>

#define BB 2
#define SS 1024
#define DDIM 512
#define HH 8
#define DH 64
#define FF 2048
#define MM (BB*SS)

// ---------------- scratch (no allocation allowed) ----------------
__device__ float g_xn[MM*DDIM];
__device__ float g_q [MM*DDIM];
__device__ float g_k [MM*DDIM];
__device__ float g_v [MM*DDIM];
__device__ float g_att[MM*DDIM];
__device__ float g_h [MM*DDIM];
__device__ float g_hn[MM*DDIM];
__device__ float g_f1[MM*FF];
__device__ float g_u [MM];
__device__ float g_lam[BB];
__device__ int   g_sp [BB];

// ---------------- lam / sparse flag ----------------
__global__ void lam_kernel(const float* __restrict__ u_prev){
    int b = threadIdx.x;
    if (b < BB){
        float lam = 10.0f * expf(-5.0f * u_prev[b]);
        g_lam[b] = lam;
        g_sp[b]  = (lam >= 1.0f) ? 1 : 0;
    }
}

// ---------------- LayerNorm ----------------
__global__ void ln_kernel(const float* __restrict__ x, const float* __restrict__ g,
                          const float* __restrict__ be, float* __restrict__ y){
    int row = blockIdx.x;
    int t = threadIdx.x;
    const float* xr = x + (size_t)row * DDIM;
    float4 v = *(const float4*)(xr + t*4);
    float s  = v.x + v.y + v.z + v.w;
    float ss = v.x*v.x + v.y*v.y + v.z*v.z + v.w*v.w;
    #pragma unroll
    for (int o = 16; o; o >>= 1){
        s  += __shfl_xor_sync(0xffffffffu, s,  o);
        ss += __shfl_xor_sync(0xffffffffu, ss, o);
    }
    __shared__ float ps[4], pss[4];
    int w = t >> 5;
    if ((t & 31) == 0){ ps[w] = s; pss[w] = ss; }
    __syncthreads();
    s  = ps[0] + ps[1] + ps[2] + ps[3];
    ss = pss[0] + pss[1] + pss[2] + pss[3];
    float mean = s * (1.0f/DDIM);
    float var  = ss * (1.0f/DDIM) - mean*mean;
    float inv  = rsqrtf(var + 1e-5f);
    float4 gv = *(const float4*)(g  + t*4);
    float4 bv = *(const float4*)(be + t*4);
    float4 o;
    o.x = (v.x - mean)*inv*gv.x + bv.x;
    o.y = (v.y - mean)*inv*gv.y + bv.y;
    o.z = (v.z - mean)*inv*gv.z + bv.z;
    o.w = (v.w - mean)*inv*gv.w + bv.w;
    *(float4*)(y + (size_t)row * DDIM + t*4) = o;
}

// ---------------- bf16 split helpers ----------------
__device__ __forceinline__ void bsplit(float x0, float x1, unsigned &hw, unsigned &lw){
    asm("cvt.rn.bf16x2.f32 %0, %1, %2;" : "=r"(hw) : "f"(x1), "f"(x0));
    float h0 = __uint_as_float(hw << 16);
    float h1 = __uint_as_float(hw & 0xffff0000u);
    float l0 = x0 - h0, l1 = x1 - h1;
    asm("cvt.rn.bf16x2.f32 %0, %1, %2;" : "=r"(lw) : "f"(l1), "f"(l0));
}

__device__ __forceinline__ void mma16(float* c, const unsigned* a, const unsigned* b){
    asm volatile(
        "mma.sync.aligned.m16n8k16.row.col.f32.bf16.bf16.f32 "
        "{%0,%1,%2,%3}, {%4,%5,%6,%7}, {%8,%9}, {%0,%1,%2,%3};\n"
        : "+f"(c[0]), "+f"(c[1]), "+f"(c[2]), "+f"(c[3])
        : "r"(a[0]), "r"(a[1]), "r"(a[2]), "r"(a[3]), "r"(b[0]), "r"(b[1]));
}

__device__ __forceinline__ float gelu_exact(float v){
    return 0.5f * v * (1.0f + erff(v * 0.70710678118654752f));
}

// ---------------- bf16x3 tensor-core GEMM body (prefetched) ----------------
template<int BM, bool GELU, bool RES>
__device__ __forceinline__ void gemm_body(
        const float* __restrict__ A, const float* __restrict__ W,
        const float* __restrict__ bias, const float* __restrict__ res,
        float* __restrict__ C, int Kn, int Nn, int m0, int n0){
    constexpr int MTILES = BM/16;
    constexpr int WMT    = MTILES/2;
    constexpr int AIT    = BM/16;

    __shared__ unsigned Ah[2][MTILES][32][4];
    __shared__ unsigned Al[2][MTILES][32][4];
    __shared__ unsigned Bh[2][8][32][2];
    __shared__ unsigned Bl[2][8][32][2];

    const int tid = threadIdx.x;
    const int warp = tid >> 5, ln = tid & 31;
    const int wm = warp >> 1, wn = warp & 1;
    const int gid = ln >> 2, t4 = ln & 3;

    float acc[WMT][4][4];
    #pragma unroll
    for (int mt = 0; mt < WMT; mt++)
        #pragma unroll
        for (int nt = 0; nt < 4; nt++)
            #pragma unroll
            for (int r = 0; r < 4; r++) acc[mt][nt][r] = 0.0f;

    float4 av[AIT], wv4[4];
    // prefetch first tile
    #pragma unroll
    for (int i = 0; i < AIT; i++){
        int f = tid + i*128;
        int row = f >> 3, kq = (f & 7) << 2;
        av[i] = *(const float4*)(A + (size_t)(m0 + row)*Kn + kq);
    }
    #pragma unroll
    for (int i = 0; i < 4; i++){
        int f = tid + i*128;
        int row = f >> 3, kq = (f & 7) << 2;
        wv4[i] = *(const float4*)(W + (size_t)(n0 + row)*Kn + kq);
    }

    for (int kt = 0; kt < Kn; kt += 32){
        __syncthreads();
        #pragma unroll
        for (int i = 0; i < AIT; i++){
            int f = tid + i*128;
            int row = f >> 3, kq = (f & 7) << 2;
            int ks = kq >> 4, kk = kq & 15;
            int mt = row >> 4, rr = row & 15;
            int slot = ((rr >> 3) & 1) + (((kk >> 3) & 1) << 1);
            int lane = (rr & 7)*4 + ((kk & 7) >> 1);
            unsigned h0, l0, h1, l1;
            bsplit(av[i].x, av[i].y, h0, l0);
            bsplit(av[i].z, av[i].w, h1, l1);
            Ah[ks][mt][lane  ][slot] = h0;
            Ah[ks][mt][lane+1][slot] = h1;
            Al[ks][mt][lane  ][slot] = l0;
            Al[ks][mt][lane+1][slot] = l1;
        }
        #pragma unroll
        for (int i = 0; i < 4; i++){
            int f = tid + i*128;
            int row = f >> 3, kq = (f & 7) << 2;
            int ks = kq >> 4, kk = kq & 15;
            int nt = row >> 3;
            int slot = (kk >> 3) & 1;
            int lane = (row & 7)*4 + ((kk & 7) >> 1);
            unsigned h0, l0, h1, l1;
            bsplit(wv4[i].x, wv4[i].y, h0, l0);
            bsplit(wv4[i].z, wv4[i].w, h1, l1);
            Bh[ks][nt][lane  ][slot] = h0;
            Bh[ks][nt][lane+1][slot] = h1;
            Bl[ks][nt][lane  ][slot] = l0;
            Bl[ks][nt][lane+1][slot] = l1;
        }
        __syncthreads();

        // prefetch next tile while MMAs run
        if (kt + 32 < Kn){
            #pragma unroll
            for (int i = 0; i < AIT; i++){
                int f = tid + i*128;
                int row = f >> 3, kq = (f & 7) << 2;
                av[i] = *(const float4*)(A + (size_t)(m0 + row)*Kn + kt + 32 + kq);
            }
            #pragma unroll
            for (int i = 0; i < 4; i++){
                int f = tid + i*128;
                int row = f >> 3, kq = (f & 7) << 2;
                wv4[i] = *(const float4*)(W + (size_t)(n0 + row)*Kn + kt + 32 + kq);
            }
        }

        #pragma unroll
        for (int ks = 0; ks < 2; ks++){
            unsigned ah[WMT][4], al[WMT][4], bh[4][2], bl[4][2];
            #pragma unroll
            for (int mt = 0; mt < WMT; mt++){
                *(uint4*)ah[mt] = *(const uint4*)Ah[ks][wm*WMT + mt][ln];
                *(uint4*)al[mt] = *(const uint4*)Al[ks][wm*WMT + mt][ln];
            }
            #pragma unroll
            for (int nt = 0; nt < 4; nt++){
                *(uint2*)bh[nt] = *(const uint2*)Bh[ks][wn*4 + nt][ln];
                *(uint2*)bl[nt] = *(const uint2*)Bl[ks][wn*4 + nt][ln];
            }
            #pragma unroll
            for (int mt = 0; mt < WMT; mt++)
                #pragma unroll
                for (int nt = 0; nt < 4; nt++){
                    mma16(acc[mt][nt], ah[mt], bh[nt]);
                    mma16(acc[mt][nt], ah[mt], bl[nt]);
                    mma16(acc[mt][nt], al[mt], bh[nt]);
                }
        }
    }

    #pragma unroll
    for (int mt = 0; mt < WMT; mt++){
        #pragma unroll
        for (int rr = 0; rr < 2; rr++){
            int m = m0 + wm*(BM/2) + mt*16 + gid + rr*8;
            #pragma unroll
            for (int nt = 0; nt < 4; nt++){
                int n = n0 + wn*32 + nt*8 + t4*2;
                float2 o;
                o.x = acc[mt][nt][rr*2 + 0];
                o.y = acc[mt][nt][rr*2 + 1];
                float2 bv = *(const float2*)(bias + n);
                o.x += bv.x; o.y += bv.y;
                if (RES){
                    float2 rv = *(const float2*)(res + (size_t)m*Nn + n);
                    o.x += rv.x; o.y += rv.y;
                }
                if (GELU){
                    o.x = gelu_exact(o.x);
                    o.y = gelu_exact(o.y);
                }
                *(float2*)(C + (size_t)m*Nn + n) = o;
            }
        }
    }
}

// ---------------- GEMM kernels ----------------
__global__ void __launch_bounds__(128)
qkv_kernel(const float* __restrict__ xn,
           const float* __restrict__ wq, const float* __restrict__ wk, const float* __restrict__ wv,
           const float* __restrict__ bq, const float* __restrict__ bk, const float* __restrict__ bv,
           float* __restrict__ q, float* __restrict__ k, float* __restrict__ v){
    int sel = blockIdx.x >> 3;
    int n0 = (blockIdx.x & 7) << 6;
    const float* W    = (sel == 0) ? wq : (sel == 1) ? wk : wv;
    const float* bias = (sel == 0) ? bq : (sel == 1) ? bk : bv;
    float* C          = (sel == 0) ? q  : (sel == 1) ? k  : v;
    gemm_body<64,false,false>(xn, W, bias, nullptr, C, DDIM, DDIM, blockIdx.y*64, n0);
}

template<bool GELU, bool RES>
__global__ void __launch_bounds__(128)
gemm64(const float* __restrict__ A, const float* __restrict__ W,
       const float* __restrict__ bias, const float* __restrict__ res,
       float* __restrict__ C, int Kn, int Nn){
    gemm_body<64,GELU,RES>(A, W, bias, res, C, Kn, Nn, blockIdx.y*64, blockIdx.x*64);
}

template<bool GELU, bool RES>
__global__ void __launch_bounds__(128)
gemm32(const float* __restrict__ A, const float* __restrict__ W,
       const float* __restrict__ bias, const float* __restrict__ res,
       float* __restrict__ C, int Kn, int Nn){
    gemm_body<32,GELU,RES>(A, W, bias, res, C, Kn, Nn, blockIdx.y*32, blockIdx.x*64);
}

// ---------------- tensor-core flash attention ----------------
// 128 threads (4 warps). Tile 64q x 64k. Warp w owns q rows [w*16, w*16+16).
// Q: persistent A-fragments (hi/lo). K: B-frag over (n=seq, k=d).
// V: B-frag over (n=d, k=seq) (transposed at staging).
// Scores C-fragment == P A-fragment layout -> softmax entirely in registers.
__global__ void __launch_bounds__(128)
attn_kernel(const float* __restrict__ Q, const float* __restrict__ K,
            const float* __restrict__ V, float* __restrict__ O){
    __shared__ unsigned Kh[4][8][32][2], Kl[4][8][32][2];
    __shared__ unsigned Vh[4][8][32][2], Vl[4][8][32][2];

    const int bh = blockIdx.y;
    const int b = bh / HH, h = bh % HH;
    const int q0 = blockIdx.x * 64;
    const float lam = g_lam[b];
    const int sp = g_sp[b];
    const int tid = threadIdx.x;
    const int w = tid >> 5, ln = tid & 31;
    const int gid = ln >> 2, t4 = ln & 3;
    const int r0 = q0 + w*16 + gid;      // global q row (c0,c1)
    const int r1 = r0 + 8;               // global q row (c2,c3)

    // persistent Q fragments
    unsigned qh[4][4], ql[4][4];
    {
        const float* Qb = Q + (size_t)(b*SS)*DDIM + h*DH;
        #pragma unroll
        for (int ks = 0; ks < 4; ks++){
            int kcol = ks*16 + t4*2;
            float2 q00 = *(const float2*)(Qb + (size_t)r0*DDIM + kcol);
            float2 q10 = *(const float2*)(Qb + (size_t)r1*DDIM + kcol);
            float2 q01 = *(const float2*)(Qb + (size_t)r0*DDIM + kcol + 8);
            float2 q11 = *(const float2*)(Qb + (size_t)r1*DDIM + kcol + 8);
            bsplit(q00.x, q00.y, qh[ks][0], ql[ks][0]);
            bsplit(q10.x, q10.y, qh[ks][1], ql[ks][1]);
            bsplit(q01.x, q01.y, qh[ks][2], ql[ks][2]);
            bsplit(q11.x, q11.y, qh[ks][3], ql[ks][3]);
        }
    }

    float oacc[8][4];
    #pragma unroll
    for (int nt = 0; nt < 8; nt++)
        #pragma unroll
        for (int r = 0; r < 4; r++) oacc[nt][r] = 0.0f;
    float mrow0 = -INFINITY, mrow1 = -INFINITY;
    float lrow0 = 0.0f, lrow1 = 0.0f;

    int klo = 0, khi = SS/64;
    if (sp){
        int lo = q0 - 51; if (lo < 0) lo = 0;
        int hi = q0 + 114; if (hi > SS-1) hi = SS-1;
        klo = lo >> 6; khi = (hi >> 6) + 1;
    }

    const float* Kb = K + (size_t)(b*SS)*DDIM + h*DH;
    const float* Vb = V + (size_t)(b*SS)*DDIM + h*DH;

    for (int kb = klo; kb < khi; kb++){
        __syncthreads();
        // stage K tile: element (seq row r, d) -> Kh[d>>4][r>>3][(r&7)*4 + (d&7)>>1][(d>>3)&1]
        #pragma unroll
        for (int i = 0; i < 4; i++){
            int f = tid + i*128;            // 0..511
            int r = f >> 3;                 // 0..63
            int d8 = (f & 7) * 8;           // 0,8,..,56
            float4 x0 = *(const float4*)(Kb + (size_t)(kb*64 + r)*DDIM + d8);
            float4 x1 = *(const float4*)(Kb + (size_t)(kb*64 + r)*DDIM + d8 + 4);
            int ks = d8 >> 4, slot = (d8 >> 3) & 1;
            int lbase = (r & 7) * 4;
            int nt = r >> 3;
            unsigned h0,l0,h1,l1,h2,l2,h3,l3;
            bsplit(x0.x, x0.y, h0, l0);
            bsplit(x0.z, x0.w, h1, l1);
            bsplit(x1.x, x1.y, h2, l2);
            bsplit(x1.z, x1.w, h3, l3);
            Kh[ks][nt][lbase+0][slot] = h0;  Kl[ks][nt][lbase+0][slot] = l0;
            Kh[ks][nt][lbase+1][slot] = h1;  Kl[ks][nt][lbase+1][slot] = l1;
            Kh[ks][nt][lbase+2][slot] = h2;  Kl[ks][nt][lbase+2][slot] = l2;
            Kh[ks][nt][lbase+3][slot] = h3;  Kl[ks][nt][lbase+3][slot] = l3;
        }
        // stage V tile transposed: element (seq s, d) -> Vh[s>>4][d>>3][(d&7)*4 + (s&7)>>1][(s>>3)&1]
        #pragma unroll
        for (int i = 0; i < 4; i++){
            int f = tid + i*128;            // 0..511
            int spr = f >> 4;               // 0..31 (seq pair)
            int d4 = (f & 15) * 4;          // 0..60
            int s = spr * 2;
            float4 x0 = *(const float4*)(Vb + (size_t)(kb*64 + s    )*DDIM + d4);
            float4 x1 = *(const float4*)(Vb + (size_t)(kb*64 + s + 1)*DDIM + d4);
            int ks = s >> 4, slot = (s >> 3) & 1;
            int tp = (s & 7) >> 1;
            float a0[4] = {x0.x, x0.y, x0.z, x0.w};
            float a1[4] = {x1.x, x1.y, x1.z, x1.w};
            #pragma unroll
            for (int j = 0; j < 4; j++){
                int d = d4 + j;
                unsigned hv, lv;
                bsplit(a0[j], a1[j], hv, lv);
                Vh[ks][d>>3][(d&7)*4 + tp][slot] = hv;
                Vl[ks][d>>3][(d&7)*4 + tp][slot] = lv;
            }
        }
        __syncthreads();

        // scores: sfrag[nt] (16q x 8k each)
        float sfrag[8][4];
        #pragma unroll
        for (int nt = 0; nt < 8; nt++)
            #pragma unroll
            for (int r = 0; r < 4; r++) sfrag[nt][r] = 0.0f;
        #pragma unroll
        for (int ks = 0; ks < 4; ks++){
            #pragma unroll
            for (int nt = 0; nt < 8; nt++){
                unsigned kh2[2], kl2[2];
                *(uint2*)kh2 = *(const uint2*)Kh[ks][nt][ln];
                *(uint2*)kl2 = *(const uint2*)Kl[ks][nt][ln];
                mma16(sfrag[nt], qh[ks], kh2);
                mma16(sfrag[nt], qh[ks], kl2);
                mma16(sfrag[nt], ql[ks], kh2);
            }
        }

        // softmax (registers only)
        float mx0 = -INFINITY, mx1 = -INFINITY;
        #pragma unroll
        for (int nt = 0; nt < 8; nt++){
            #pragma unroll
            for (int e = 0; e < 2; e++){
                int c = kb*64 + nt*8 + t4*2 + e;
                bool in0 = (c >= r0 - 51) && (c <= r0 + 51);
                bool in1 = (c >= r1 - 51) && (c <= r1 + 51);
                float v0 = sfrag[nt][e]   * 0.125f;
                float v1 = sfrag[nt][2+e] * 0.125f;
                if (sp){
                    v0 = in0 ? v0 : -INFINITY;
                    v1 = in1 ? v1 : -INFINITY;
                } else {
                    if (!in0) v0 -= lam;
                    if (!in1) v1 -= lam;
                }
                sfrag[nt][e]   = v0;
                sfrag[nt][2+e] = v1;
                mx0 = fmaxf(mx0, v0);
                mx1 = fmaxf(mx1, v1);
            }
        }
        #pragma unroll
        for (int o = 1; o <= 2; o <<= 1){
            mx0 = fmaxf(mx0, __shfl_xor_sync(0xffffffffu, mx0, o));
            mx1 = fmaxf(mx1, __shfl_xor_sync(0xffffffffu, mx1, o));
        }
        float mnew0 = fmaxf(mrow0, mx0);
        float mnew1 = fmaxf(mrow1, mx1);
        float sf0 = (mrow0 == mnew0) ? 1.0f : __expf(mrow0 - mnew0);
        float sf1 = (mrow1 == mnew1) ? 1.0f : __expf(mrow1 - mnew1);
        float mc0 = fmaxf(mnew0, -1e30f);
        float mc1 = fmaxf(mnew1, -1e30f);
        float rs0 = 0.0f, rs1 = 0.0f;
        #pragma unroll
        for (int nt = 0; nt < 8; nt++){
            #pragma unroll
            for (int e = 0; e < 2; e++){
                float p0 = __expf(sfrag[nt][e]   - mc0);
                float p1 = __expf(sfrag[nt][2+e] - mc1);
                sfrag[nt][e]   = p0;
                sfrag[nt][2+e] = p1;
                rs0 += p0; rs1 += p1;
            }
        }
        #pragma unroll
        for (int o = 1; o <= 2; o <<= 1){
            rs0 += __shfl_xor_sync(0xffffffffu, rs0, o);
            rs1 += __shfl_xor_sync(0xffffffffu, rs1, o);
        }
        lrow0 = lrow0 * sf0 + rs0;  mrow0 = mnew0;
        lrow1 = lrow1 * sf1 + rs1;  mrow1 = mnew1;
        #pragma unroll
        for (int nt = 0; nt < 8; nt++){
            oacc[nt][0] *= sf0; oacc[nt][1] *= sf0;
            oacc[nt][2] *= sf1; oacc[nt][3] *= sf1;
        }

        // P @ V : P is already in A-fragment layout
        #pragma unroll
        for (int pks = 0; pks < 4; pks++){
            unsigned pah[4], pal[4];
            bsplit(sfrag[2*pks  ][0], sfrag[2*pks  ][1], pah[0], pal[0]);
            bsplit(sfrag[2*pks  ][2], sfrag[2*pks  ][3], pah[1], pal[1]);
            bsplit(sfrag[2*pks+1][0], sfrag[2*pks+1][1], pah[2], pal[2]);
            bsplit(sfrag[2*pks+1][2], sfrag[2*pks+1][3], pah[3], pal[3]);
            #pragma unroll
            for (int nt = 0; nt < 8; nt++){
                unsigned vh2[2], vl2[2];
                *(uint2*)vh2 = *(const uint2*)Vh[pks][nt][ln];
                *(uint2*)vl2 = *(const uint2*)Vl[pks][nt][ln];
                mma16(oacc[nt], pah, vh2);
                mma16(oacc[nt], pah, vl2);
                mma16(oacc[nt], pal, vh2);
            }
        }
    }

    // epilogue
    float inv0 = 1.0f / lrow0;
    float inv1 = 1.0f / lrow1;
    float* Ob = O + (size_t)(b*SS)*DDIM + h*DH;
    #pragma unroll
    for (int nt = 0; nt < 8; nt++){
        int d = nt*8 + t4*2;
        float2 o0, o1;
        o0.x = oacc[nt][0]*inv0; o0.y = oacc[nt][1]*inv0;
        o1.x = oacc[nt][2]*inv1; o1.y = oacc[nt][3]*inv1;
        *(float2*)(Ob + (size_t)r0*DDIM + d) = o0;
        *(float2*)(Ob + (size_t)r1*DDIM + d) = o1;
    }
}

// ---------------- per-row u, then per-batch mean ----------------
__global__ void u_row_kernel(const float* __restrict__ outp, const float* __restrict__ x){
    int row = blockIdx.x;
    int t = threadIdx.x;
    float4 ov = *(const float4*)(outp + (size_t)row*DDIM + t*4);
    float4 xv = *(const float4*)(x    + (size_t)row*DDIM + t*4);
    float dx = ov.x - xv.x, dy = ov.y - xv.y, dz = ov.z - xv.z, dw = ov.w - xv.w;
    float d2 = dx*dx + dy*dy + dz*dz + dw*dw;
    float x2 = xv.x*xv.x + xv.y*xv.y + xv.z*xv.z + xv.w*xv.w;
    #pragma unroll
    for (int o = 16; o; o >>= 1){
        d2 += __shfl_xor_sync(0xffffffffu, d2, o);
        x2 += __shfl_xor_sync(0xffffffffu, x2, o);
    }
    __shared__ float pd[4], px[4];
    int w = t >> 5;
    if ((t & 31) == 0){ pd[w] = d2; px[w] = x2; }
    __syncthreads();
    if (t == 0){
        d2 = pd[0]+pd[1]+pd[2]+pd[3];
        x2 = px[0]+px[1]+px[2]+px[3];
        g_u[row] = sqrtf(d2) / (sqrtf(x2) + 1e-8f);
    }
}

__global__ void u_mean_kernel(float* __restrict__ outp, int out_size){
    int b = blockIdx.x;
    int t = threadIdx.x;
    float s = 0.0f;
    for (int i = t; i < SS; i += 256) s += g_u[b*SS + i];
    #pragma unroll
    for (int o = 16; o; o >>= 1) s += __shfl_xor_sync(0xffffffffu, s, o);
    __shared__ float ps[8];
    int w = t >> 5;
    if ((t & 31) == 0) ps[w] = s;
    __syncthreads();
    if (t == 0){
        s = 0.0f;
        #pragma unroll
        for (int i = 0; i < 8; i++) s += ps[i];
        int idx = MM*DDIM + b;
        if (idx < out_size) outp[idx] = s * (1.0f/SS);
    }
}

// ---------------- launch ----------------
extern "C" void kernel_launch(void* const* d_in, const int* in_sizes, int n_in,
                              void* d_out, int out_size){
    const float* x      = (const float*)d_in[0];
    const float* u_prev = (const float*)d_in[1];
    const float* wq = (const float*)d_in[2];  const float* bq = (const float*)d_in[3];
    const float* wk = (const float*)d_in[4];  const float* bk = (const float*)d_in[5];
    const float* wv = (const float*)d_in[6];  const float* bv = (const float*)d_in[7];
    const float* wo = (const float*)d_in[8];  const float* bo = (const float*)d_in[9];
    const float* ln1g = (const float*)d_in[10]; const float* ln1b = (const float*)d_in[11];
    const float* ln2g = (const float*)d_in[12]; const float* ln2b = (const float*)d_in[13];
    const float* w1 = (const float*)d_in[14]; const float* b1 = (const float*)d_in[15];
    const float* w2 = (const float*)d_in[16]; const float* b2 = (const float*)d_in[17];
    float* outp = (float*)d_out;

    float *p_xn, *p_q, *p_k, *p_v, *p_att, *p_h, *p_hn, *p_f1;
    cudaGetSymbolAddress((void**)&p_xn,  g_xn);
    cudaGetSymbolAddress((void**)&p_q,   g_q);
    cudaGetSymbolAddress((void**)&p_k,   g_k);
    cudaGetSymbolAddress((void**)&p_v,   g_v);
    cudaGetSymbolAddress((void**)&p_att, g_att);
    cudaGetSymbolAddress((void**)&p_h,   g_h);
    cudaGetSymbolAddress((void**)&p_hn,  g_hn);
    cudaGetSymbolAddress((void**)&p_f1,  g_f1);

    lam_kernel<<<1, 32>>>(u_prev);
    ln_kernel<<<MM, 128>>>(x, ln1g, ln1b, p_xn);

    qkv_kernel<<<dim3(24, MM/64), 128>>>(p_xn, wq, wk, wv, bq, bk, bv, p_q, p_k, p_v);

    attn_kernel<<<dim3(SS/64, BB*HH), 128>>>(p_q, p_k, p_v, p_att);

    gemm32<false,true><<<dim3(DDIM/64, MM/32), 128>>>(p_att, wo, bo, x, p_h, DDIM, DDIM);

    ln_kernel<<<MM, 128>>>(p_h, ln2g, ln2b, p_hn);

    gemm64<true,false><<<dim3(FF/64, MM/64), 128>>>(p_hn, w1, b1, nullptr, p_f1, DDIM, FF);
    gemm32<false,true><<<dim3(DDIM/64, MM/32), 128>>>(p_f1, w2, b2, p_h, outp, FF, DDIM);

    u_row_kernel<<<MM, 128>>>(outp, x);
    u_mean_kernel<<<BB, 256>>>(outp, out_size);
}